// round 2
// baseline (speedup 1.0000x reference)
#include <cuda_runtime.h>

// Problem constants
#define PB   2
#define PS   1024
#define PHQ  32
#define PHKV 8
#define PG   (PHQ / PHKV)   // 4
#define PD   128

#define BM 64
#define BN 64
#define NT 256

#define QSTR (PD + 4)   // 132 floats
#define KSTR (PD + 4)   // 132
#define SSTR (BN + 4)   // 68
#define VSTR (BN + 4)   // 68

#define SM_QS   0
#define SM_KS   (BM * QSTR)                    // 8448
#define SM_VST  (SM_KS + BN * KSTR)            // 16896
#define SM_SS   (SM_VST + PD * VSTR)           // 25600
#define SM_FLOATS (SM_SS + BM * SSTR)          // 29952
#define SMEM_BYTES (SM_FLOATS * 4)             // 119808

#define SCALE 0.08838834764831845f
#define NEGINF (-1e30f)

// ---------------------------------------------------------------------------
// Flash attention: one CTA per (q-tile, head, batch). 256 threads.
// Thread (tx,ty): tx = tid&15, ty = tid>>4.
// QK micro-tile: rows {ty+16i, i<4}, cols {tx+16j, j<4}.
// PV/O micro-tile: rows {ty+16i, i<4}, cols {tx+16jo, jo<8}.
// ---------------------------------------------------------------------------
__global__ __launch_bounds__(NT, 1)
void attn_kernel(const float* __restrict__ xq, const float* __restrict__ xk,
                 const float* __restrict__ xv, float* __restrict__ out)
{
    extern __shared__ float sm[];
    float* Qs  = sm + SM_QS;
    float* Ks  = sm + SM_KS;
    float* Vst = sm + SM_VST;
    float* Ss  = sm + SM_SS;

    const int qt = blockIdx.x;
    const int h  = blockIdx.y;
    const int b  = blockIdx.z;
    const int hk = h / PG;
    const int tid = threadIdx.x;
    const int tx = tid & 15;
    const int ty = tid >> 4;

    const int q0 = qt * BM;

    // ---- Load Q tile (pre-scaled) ----
    {
        const float* qbase = xq + ((size_t)(b * PS + q0) * PHQ + h) * PD;
        #pragma unroll
        for (int it = 0; it < (BM * PD / 4) / NT; ++it) {   // 8 iters
            int idx = tid + it * NT;
            int r = idx >> 5;           // 32 float4 per row
            int c4 = idx & 31;
            float4 v = *(const float4*)(qbase + (size_t)r * PHQ * PD + c4 * 4);
            v.x *= SCALE; v.y *= SCALE; v.z *= SCALE; v.w *= SCALE;
            *(float4*)(&Qs[r * QSTR + c4 * 4]) = v;
        }
    }

    float acc[4][8];
    #pragma unroll
    for (int i = 0; i < 4; ++i)
        #pragma unroll
        for (int jo = 0; jo < 8; ++jo) acc[i][jo] = 0.f;
    float mrow[4], lrow[4];
    #pragma unroll
    for (int i = 0; i < 4; ++i) { mrow[i] = NEGINF; lrow[i] = 0.f; }

    for (int kt = 0; kt <= qt; ++kt) {
        const int k0 = kt * BN;
        __syncthreads();   // Qs ready (iter 0); Ks/Vst/Ss consumed (iter>0)

        // ---- Load K tile ----
        {
            const float* kbase = xk + ((size_t)(b * PS + k0) * PHKV + hk) * PD;
            #pragma unroll
            for (int it = 0; it < (BN * PD / 4) / NT; ++it) {  // 8
                int idx = tid + it * NT;
                int r = idx >> 5;
                int c4 = idx & 31;
                float4 v = *(const float4*)(kbase + (size_t)r * PHKV * PD + c4 * 4);
                *(float4*)(&Ks[r * KSTR + c4 * 4]) = v;
            }
        }
        // ---- Load V tile, transposed: Vst[d][j] ----
        {
            const float* vbase = xv + ((size_t)(b * PS + k0) * PHKV + hk) * PD;
            #pragma unroll
            for (int it = 0; it < (BN * PD / 4) / NT; ++it) {  // 8
                int idx = tid + it * NT;
                int r = idx >> 5;
                int c4 = idx & 31;
                float4 v = *(const float4*)(vbase + (size_t)r * PHKV * PD + c4 * 4);
                Vst[(c4 * 4 + 0) * VSTR + r] = v.x;
                Vst[(c4 * 4 + 1) * VSTR + r] = v.y;
                Vst[(c4 * 4 + 2) * VSTR + r] = v.z;
                Vst[(c4 * 4 + 3) * VSTR + r] = v.w;
            }
        }
        __syncthreads();

        // ---- S = Q @ K^T (scaled) ----
        float c[4][4];
        #pragma unroll
        for (int i = 0; i < 4; ++i)
            #pragma unroll
            for (int j = 0; j < 4; ++j) c[i][j] = 0.f;

        #pragma unroll 4
        for (int k = 0; k < PD; k += 4) {
            float4 a[4], bb[4];
            #pragma unroll
            for (int i = 0; i < 4; ++i)
                a[i] = *(const float4*)(&Qs[(ty + 16 * i) * QSTR + k]);
            #pragma unroll
            for (int j = 0; j < 4; ++j)
                bb[j] = *(const float4*)(&Ks[(tx + 16 * j) * KSTR + k]);
            #pragma unroll
            for (int i = 0; i < 4; ++i)
                #pragma unroll
                for (int j = 0; j < 4; ++j) {
                    c[i][j] += a[i].x * bb[j].x;
                    c[i][j] += a[i].y * bb[j].y;
                    c[i][j] += a[i].z * bb[j].z;
                    c[i][j] += a[i].w * bb[j].w;
                }
        }

        // ---- Causal mask (diagonal tile only) ----
        if (kt == qt) {
            #pragma unroll
            for (int i = 0; i < 4; ++i) {
                int qr = q0 + ty + 16 * i;
                #pragma unroll
                for (int j = 0; j < 4; ++j) {
                    int kc = k0 + tx + 16 * j;
                    if (kc > qr) c[i][j] = NEGINF;
                }
            }
        }

        // ---- Online softmax ----
        #pragma unroll
        for (int i = 0; i < 4; ++i) {
            float mx = fmaxf(fmaxf(c[i][0], c[i][1]), fmaxf(c[i][2], c[i][3]));
            #pragma unroll
            for (int o = 1; o < 16; o <<= 1)
                mx = fmaxf(mx, __shfl_xor_sync(0xffffffffu, mx, o));
            float mnew = fmaxf(mrow[i], mx);
            float alpha = __expf(mrow[i] - mnew);
            float ssum = 0.f;
            #pragma unroll
            for (int j = 0; j < 4; ++j) {
                float p = __expf(c[i][j] - mnew);
                c[i][j] = p;
                ssum += p;
            }
            #pragma unroll
            for (int o = 1; o < 16; o <<= 1)
                ssum += __shfl_xor_sync(0xffffffffu, ssum, o);
            lrow[i] = lrow[i] * alpha + ssum;
            mrow[i] = mnew;
            #pragma unroll
            for (int jo = 0; jo < 8; ++jo) acc[i][jo] *= alpha;
            #pragma unroll
            for (int j = 0; j < 4; ++j)
                Ss[(ty + 16 * i) * SSTR + tx + 16 * j] = c[i][j];
        }
        __syncthreads();

        // ---- O += P @ V ----
        #pragma unroll 2
        for (int k = 0; k < BN; k += 4) {
            float4 a[4], bb[8];
            #pragma unroll
            for (int i = 0; i < 4; ++i)
                a[i] = *(const float4*)(&Ss[(ty + 16 * i) * SSTR + k]);
            #pragma unroll
            for (int jo = 0; jo < 8; ++jo)
                bb[jo] = *(const float4*)(&Vst[(tx + 16 * jo) * VSTR + k]);
            #pragma unroll
            for (int i = 0; i < 4; ++i)
                #pragma unroll
                for (int jo = 0; jo < 8; ++jo) {
                    acc[i][jo] += a[i].x * bb[jo].x;
                    acc[i][jo] += a[i].y * bb[jo].y;
                    acc[i][jo] += a[i].z * bb[jo].z;
                    acc[i][jo] += a[i].w * bb[jo].w;
                }
        }
    }

    // ---- Epilogue: O / l ----
    #pragma unroll
    for (int i = 0; i < 4; ++i) {
        float inv = 1.f / lrow[i];
        int qr = q0 + ty + 16 * i;
        float* obase = out + ((size_t)(b * PS + qr) * PHQ + h) * PD;
        #pragma unroll
        for (int jo = 0; jo < 8; ++jo)
            obase[tx + 16 * jo] = acc[i][jo] * inv;
    }
}

// ---------------------------------------------------------------------------
// KV-cache scatter: kv_out[sel[i]] = concat(xk_row_i, xv_row_i)
// Grid covers B*S rows x 512 float4 per row.
// ---------------------------------------------------------------------------
__global__ void kv_scatter_kernel(const float* __restrict__ xk,
                                  const float* __restrict__ xv,
                                  const int* __restrict__ sel,
                                  float* __restrict__ kv_out)
{
    int idx = blockIdx.x * blockDim.x + threadIdx.x;   // over (B*S)*512 float4
    int row = idx >> 9;       // / 512
    int w   = idx & 511;
    if (row >= PB * PS) return;
    int dst = sel[row];
    float4 v;
    if (w < 256) {
        v = ((const float4*)xk)[row * 256 + w];
    } else {
        v = ((const float4*)xv)[row * 256 + (w - 256)];
    }
    ((float4*)kv_out)[(size_t)dst * 512 + w] = v;
}

// ---------------------------------------------------------------------------
extern "C" void kernel_launch(void* const* d_in, const int* in_sizes, int n_in,
                              void* d_out, int out_size)
{
    const float* xq    = (const float*)d_in[0];
    const float* xk    = (const float*)d_in[1];
    const float* xv    = (const float*)d_in[2];
    const float* kvbuf = (const float*)d_in[3];
    const int*   sel   = (const int*)d_in[4];
    float* out = (float*)d_out;

    const size_t attn_elems = (size_t)PB * PS * PHQ * PD;          // 8388608
    const size_t kv_elems   = (size_t)PB * PS * 2 * PHKV * PD;     // 4194304

    // Allow >48KB dynamic smem. Unconditional (no static guard), idempotent,
    // not a stream op — safe under graph capture.
    cudaFuncSetAttribute(attn_kernel,
                         cudaFuncAttributeMaxDynamicSharedMemorySize,
                         SMEM_BYTES);

    dim3 grid(PS / BM, PHQ, PB);
    attn_kernel<<<grid, NT, SMEM_BYTES>>>(xq, xk, xv, out);

    if ((size_t)out_size >= attn_elems + kv_elems) {
        float* kv_out = out + attn_elems;
        // base copy of kv_buffer (covers rows not touched by scatter)
        cudaMemcpyAsync(kv_out, kvbuf, kv_elems * sizeof(float),
                        cudaMemcpyDeviceToDevice);
        int total4 = PB * PS * 512;
        kv_scatter_kernel<<<(total4 + 255) / 256, 256>>>(xk, xv, sel, kv_out);
    }
}

// round 3
// speedup vs baseline: 3.4043x; 3.4043x over previous
#include <cuda_runtime.h>
#include <cuda_bf16.h>

// Problem constants
#define PB   2
#define PS   1024
#define PHQ  32
#define PHKV 8
#define PG   (PHQ / PHKV)   // 4
#define PD   128

#define BM 64
#define BN 64
#define NT 128              // 4 warps; each warp owns a 16-row stripe

#define SCALE 0.08838834764831845f
#define NEGINF (-1e30f)

#define STR 136             // bf16 smem row stride (128 + 8 pad) -> conflict-free ldmatrix

// smem offsets in bf16 elements
#define SM_QH 0
#define SM_QL (SM_QH + BM * STR)
#define SM_KH (SM_QL + BM * STR)
#define SM_KL (SM_KH + BN * STR)
#define SM_VH (SM_KL + BN * STR)
#define SM_VL (SM_VH + BN * STR)
#define SM_TOT (SM_VL + BN * STR)        // 6 * 8704 = 52224 bf16
#define SMEM_BYTES (SM_TOT * 2)          // 104448 bytes -> 2 CTAs/SM possible

// ---------------------------------------------------------------------------
// PTX helpers
// ---------------------------------------------------------------------------
__device__ __forceinline__ void ldsm4(unsigned* r, unsigned addr) {
    asm volatile("ldmatrix.sync.aligned.m8n8.x4.shared.b16 {%0,%1,%2,%3}, [%4];"
                 : "=r"(r[0]), "=r"(r[1]), "=r"(r[2]), "=r"(r[3]) : "r"(addr));
}
__device__ __forceinline__ void ldsm4t(unsigned* r, unsigned addr) {
    asm volatile("ldmatrix.sync.aligned.m8n8.x4.trans.shared.b16 {%0,%1,%2,%3}, [%4];"
                 : "=r"(r[0]), "=r"(r[1]), "=r"(r[2]), "=r"(r[3]) : "r"(addr));
}
__device__ __forceinline__ void mma_bf16(float* c, const unsigned* a, const unsigned* b) {
    asm volatile(
        "mma.sync.aligned.m16n8k16.row.col.f32.bf16.bf16.f32 "
        "{%0,%1,%2,%3}, {%4,%5,%6,%7}, {%8,%9}, {%0,%1,%2,%3};"
        : "+f"(c[0]), "+f"(c[1]), "+f"(c[2]), "+f"(c[3])
        : "r"(a[0]), "r"(a[1]), "r"(a[2]), "r"(a[3]), "r"(b[0]), "r"(b[1]));
}

// Split fp32 pair into (hi, lo) bf16x2 packed registers: x = hi + lo, |lo| <~ 2^-8 |x|
__device__ __forceinline__ void split2(float x0, float x1, unsigned& hi, unsigned& lo) {
    __nv_bfloat16 h0 = __float2bfloat16(x0);
    __nv_bfloat16 h1 = __float2bfloat16(x1);
    float r0 = x0 - __bfloat162float(h0);
    float r1 = x1 - __bfloat162float(h1);
    __nv_bfloat162 H(h0, h1);
    __nv_bfloat162 L(__float2bfloat16(r0), __float2bfloat16(r1));
    hi = *reinterpret_cast<unsigned*>(&H);
    lo = *reinterpret_cast<unsigned*>(&L);
}

// ---------------------------------------------------------------------------
// Flash attention, tensor-core path (split-bf16, 3-term for fp32-like accuracy)
// One CTA per (q-tile=64, head, batch). 4 warps, warp w owns rows [16w,16w+16).
// S tile kept in registers (QK C-frag == PV A-frag layout).
// ---------------------------------------------------------------------------
__global__ __launch_bounds__(NT)
void attn_kernel(const float* __restrict__ xq, const float* __restrict__ xk,
                 const float* __restrict__ xv, float* __restrict__ out)
{
    extern __shared__ __nv_bfloat16 sm[];
    const unsigned smb = (unsigned)__cvta_generic_to_shared(sm);

    const int qt = blockIdx.x;
    const int h  = blockIdx.y;
    const int b  = blockIdx.z;
    const int hk = h / PG;
    const int tid  = threadIdx.x;
    const int lane = tid & 31;
    const int wid  = tid >> 5;
    const int q0 = qt * BM;
    const int m0 = wid * 16;

    // ---- Load Q tile once (pre-scaled), split to hi/lo bf16 ----
    {
        const float* qbase = xq + ((size_t)(b * PS + q0) * PHQ + h) * PD;
        #pragma unroll
        for (int it = 0; it < (BM * PD / 4) / NT; ++it) {   // 16 iters
            int idx = tid + it * NT;
            int r = idx >> 5;
            int c4 = idx & 31;
            float4 v = *(const float4*)(qbase + (size_t)r * (PHQ * PD) + c4 * 4);
            v.x *= SCALE; v.y *= SCALE; v.z *= SCALE; v.w *= SCALE;
            unsigned h01, l01, h23, l23;
            split2(v.x, v.y, h01, l01);
            split2(v.z, v.w, h23, l23);
            int o = r * STR + c4 * 4;
            *(unsigned*)(sm + SM_QH + o)     = h01;
            *(unsigned*)(sm + SM_QH + o + 2) = h23;
            *(unsigned*)(sm + SM_QL + o)     = l01;
            *(unsigned*)(sm + SM_QL + o + 2) = l23;
        }
    }

    // Output accumulators: 16 n-blocks of m16n8 C-frags
    float oc[16][4];
    #pragma unroll
    for (int nb = 0; nb < 16; ++nb)
        #pragma unroll
        for (int j = 0; j < 4; ++j) oc[nb][j] = 0.f;
    float mr0 = NEGINF, mr1 = NEGINF, lr0 = 0.f, lr1 = 0.f;

    // ldmatrix lane addressing (element offsets within a tile)
    const int a_row = lane & 15;                 // A frag row
    const int a_col = (lane >> 4) << 3;          // A frag col half
    const int kb_r  = (lane & 7) + ((lane >> 4) << 3);      // K B-frag row part
    const int kb_c  = ((lane >> 3) & 1) << 3;               // K B-frag col half
    const int vb_r  = (lane & 7) + (((lane >> 3) & 1) << 3);// V B-frag row part
    const int vb_c  = (lane >> 4) << 3;                     // V B-frag col half

    for (int kt = 0; kt <= qt; ++kt) {
        const int k0 = kt * BN;
        __syncthreads();   // K/V smem consumed from previous iter (Q ready iter 0)

        // ---- Load K & V tiles, split to hi/lo bf16 ----
        {
            const float* kbase = xk + ((size_t)(b * PS + k0) * PHKV + hk) * PD;
            const float* vbase = xv + ((size_t)(b * PS + k0) * PHKV + hk) * PD;
            #pragma unroll
            for (int it = 0; it < (BN * PD / 4) / NT; ++it) {  // 16 iters
                int idx = tid + it * NT;
                int r = idx >> 5;
                int c4 = idx & 31;
                int o = r * STR + c4 * 4;
                float4 v = *(const float4*)(kbase + (size_t)r * (PHKV * PD) + c4 * 4);
                unsigned h01, l01, h23, l23;
                split2(v.x, v.y, h01, l01);
                split2(v.z, v.w, h23, l23);
                *(unsigned*)(sm + SM_KH + o)     = h01;
                *(unsigned*)(sm + SM_KH + o + 2) = h23;
                *(unsigned*)(sm + SM_KL + o)     = l01;
                *(unsigned*)(sm + SM_KL + o + 2) = l23;
                v = *(const float4*)(vbase + (size_t)r * (PHKV * PD) + c4 * 4);
                split2(v.x, v.y, h01, l01);
                split2(v.z, v.w, h23, l23);
                *(unsigned*)(sm + SM_VH + o)     = h01;
                *(unsigned*)(sm + SM_VH + o + 2) = h23;
                *(unsigned*)(sm + SM_VL + o)     = l01;
                *(unsigned*)(sm + SM_VL + o + 2) = l23;
            }
        }
        __syncthreads();

        // ---- S = Q @ K^T : 8 n-blocks of m16n8, K dim = 128 (8 ksteps of 16) ----
        float sc[8][4];
        #pragma unroll
        for (int nb = 0; nb < 8; ++nb)
            #pragma unroll
            for (int j = 0; j < 4; ++j) sc[nb][j] = 0.f;

        #pragma unroll
        for (int ks = 0; ks < 8; ++ks) {
            const int kc = ks * 16;
            unsigned ah[4], al[4], bh[16], bl[16];
            ldsm4(ah, smb + (SM_QH + (m0 + a_row) * STR + kc + a_col) * 2);
            ldsm4(al, smb + (SM_QL + (m0 + a_row) * STR + kc + a_col) * 2);
            #pragma unroll
            for (int nbp = 0; nbp < 4; ++nbp) {
                ldsm4(&bh[nbp * 4], smb + (SM_KH + (nbp * 16 + kb_r) * STR + kc + kb_c) * 2);
                ldsm4(&bl[nbp * 4], smb + (SM_KL + (nbp * 16 + kb_r) * STR + kc + kb_c) * 2);
            }
            #pragma unroll
            for (int nb = 0; nb < 8; ++nb) mma_bf16(sc[nb], ah, &bh[nb * 2]);
            #pragma unroll
            for (int nb = 0; nb < 8; ++nb) mma_bf16(sc[nb], al, &bh[nb * 2]);
            #pragma unroll
            for (int nb = 0; nb < 8; ++nb) mma_bf16(sc[nb], ah, &bl[nb * 2]);
        }

        // ---- Causal mask (diagonal tile only) ----
        const int r0 = lane >> 2;                 // local row within 16
        const int qr0 = q0 + m0 + r0;
        const int qr1 = qr0 + 8;
        if (kt == qt) {
            #pragma unroll
            for (int nb = 0; nb < 8; ++nb) {
                int n = k0 + nb * 8 + ((lane & 3) << 1);
                if (n     > qr0) sc[nb][0] = NEGINF;
                if (n + 1 > qr0) sc[nb][1] = NEGINF;
                if (n     > qr1) sc[nb][2] = NEGINF;
                if (n + 1 > qr1) sc[nb][3] = NEGINF;
            }
        }

        // ---- Online softmax (rows r0 and r0+8; 4 threads/row share via shfl) ----
        float mx0 = NEGINF, mx1 = NEGINF;
        #pragma unroll
        for (int nb = 0; nb < 8; ++nb) {
            mx0 = fmaxf(mx0, fmaxf(sc[nb][0], sc[nb][1]));
            mx1 = fmaxf(mx1, fmaxf(sc[nb][2], sc[nb][3]));
        }
        mx0 = fmaxf(mx0, __shfl_xor_sync(0xffffffffu, mx0, 1));
        mx0 = fmaxf(mx0, __shfl_xor_sync(0xffffffffu, mx0, 2));
        mx1 = fmaxf(mx1, __shfl_xor_sync(0xffffffffu, mx1, 1));
        mx1 = fmaxf(mx1, __shfl_xor_sync(0xffffffffu, mx1, 2));
        float mn0 = fmaxf(mr0, mx0), mn1 = fmaxf(mr1, mx1);
        float al0 = __expf(mr0 - mn0), al1 = __expf(mr1 - mn1);
        float s0 = 0.f, s1 = 0.f;
        #pragma unroll
        for (int nb = 0; nb < 8; ++nb) {
            sc[nb][0] = __expf(sc[nb][0] - mn0); s0 += sc[nb][0];
            sc[nb][1] = __expf(sc[nb][1] - mn0); s0 += sc[nb][1];
            sc[nb][2] = __expf(sc[nb][2] - mn1); s1 += sc[nb][2];
            sc[nb][3] = __expf(sc[nb][3] - mn1); s1 += sc[nb][3];
        }
        s0 += __shfl_xor_sync(0xffffffffu, s0, 1);
        s0 += __shfl_xor_sync(0xffffffffu, s0, 2);
        s1 += __shfl_xor_sync(0xffffffffu, s1, 1);
        s1 += __shfl_xor_sync(0xffffffffu, s1, 2);
        lr0 = lr0 * al0 + s0; lr1 = lr1 * al1 + s1;
        mr0 = mn0; mr1 = mn1;
        #pragma unroll
        for (int nb = 0; nb < 16; ++nb) {
            oc[nb][0] *= al0; oc[nb][1] *= al0;
            oc[nb][2] *= al1; oc[nb][3] *= al1;
        }

        // ---- O += P @ V : P in regs (C-frag -> A-frag), V via ldmatrix.trans ----
        #pragma unroll
        for (int kk = 0; kk < 4; ++kk) {          // k = kk*16 over BN
            unsigned pah[4], pal[4];
            split2(sc[2 * kk][0],     sc[2 * kk][1],     pah[0], pal[0]);
            split2(sc[2 * kk][2],     sc[2 * kk][3],     pah[1], pal[1]);
            split2(sc[2 * kk + 1][0], sc[2 * kk + 1][1], pah[2], pal[2]);
            split2(sc[2 * kk + 1][2], sc[2 * kk + 1][3], pah[3], pal[3]);
            #pragma unroll
            for (int half = 0; half < 2; ++half) {   // n-blocks 0..7, 8..15
                unsigned bh[16], bl[16];
                #pragma unroll
                for (int nbp = 0; nbp < 4; ++nbp) {
                    int ncol = half * 64 + nbp * 16 + vb_c;
                    ldsm4t(&bh[nbp * 4], smb + (SM_VH + (kk * 16 + vb_r) * STR + ncol) * 2);
                    ldsm4t(&bl[nbp * 4], smb + (SM_VL + (kk * 16 + vb_r) * STR + ncol) * 2);
                }
                #pragma unroll
                for (int j = 0; j < 8; ++j) mma_bf16(oc[half * 8 + j], pah, &bh[j * 2]);
                #pragma unroll
                for (int j = 0; j < 8; ++j) mma_bf16(oc[half * 8 + j], pal, &bh[j * 2]);
                #pragma unroll
                for (int j = 0; j < 8; ++j) mma_bf16(oc[half * 8 + j], pah, &bl[j * 2]);
            }
        }
    }

    // ---- Epilogue: O / l ----
    {
        const int r0 = lane >> 2;
        const float inv0 = 1.f / lr0, inv1 = 1.f / lr1;
        const int qrA = q0 + m0 + r0;
        const int qrB = qrA + 8;
        float* oA = out + ((size_t)(b * PS + qrA) * PHQ + h) * PD;
        float* oB = out + ((size_t)(b * PS + qrB) * PHQ + h) * PD;
        #pragma unroll
        for (int nb = 0; nb < 16; ++nb) {
            int n = nb * 8 + ((lane & 3) << 1);
            *(float2*)(oA + n) = make_float2(oc[nb][0] * inv0, oc[nb][1] * inv0);
            *(float2*)(oB + n) = make_float2(oc[nb][2] * inv1, oc[nb][3] * inv1);
        }
    }
}

// ---------------------------------------------------------------------------
// KV-cache scatter: kv_out[sel[i]] = concat(xk_row_i, xv_row_i)
// ---------------------------------------------------------------------------
__global__ void kv_scatter_kernel(const float* __restrict__ xk,
                                  const float* __restrict__ xv,
                                  const int* __restrict__ sel,
                                  float* __restrict__ kv_out)
{
    int idx = blockIdx.x * blockDim.x + threadIdx.x;   // over (B*S)*512 float4
    int row = idx >> 9;
    int w   = idx & 511;
    if (row >= PB * PS) return;
    int dst = sel[row];
    float4 v;
    if (w < 256) {
        v = ((const float4*)xk)[row * 256 + w];
    } else {
        v = ((const float4*)xv)[row * 256 + (w - 256)];
    }
    ((float4*)kv_out)[(size_t)dst * 512 + w] = v;
}

// ---------------------------------------------------------------------------
extern "C" void kernel_launch(void* const* d_in, const int* in_sizes, int n_in,
                              void* d_out, int out_size)
{
    const float* xq    = (const float*)d_in[0];
    const float* xk    = (const float*)d_in[1];
    const float* xv    = (const float*)d_in[2];
    const float* kvbuf = (const float*)d_in[3];
    const int*   sel   = (const int*)d_in[4];
    float* out = (float*)d_out;

    const size_t attn_elems = (size_t)PB * PS * PHQ * PD;          // 8388608
    const size_t kv_elems   = (size_t)PB * PS * 2 * PHKV * PD;     // 4194304

    cudaFuncSetAttribute(attn_kernel,
                         cudaFuncAttributeMaxDynamicSharedMemorySize,
                         SMEM_BYTES);

    dim3 grid(PS / BM, PHQ, PB);
    attn_kernel<<<grid, NT, SMEM_BYTES>>>(xq, xk, xv, out);

    if ((size_t)out_size >= attn_elems + kv_elems) {
        float* kv_out = out + attn_elems;
        cudaMemcpyAsync(kv_out, kvbuf, kv_elems * sizeof(float),
                        cudaMemcpyDeviceToDevice);
        int total4 = PB * PS * 512;
        kv_scatter_kernel<<<(total4 + 255) / 256, 256>>>(xk, xv, sel, kv_out);
    }
}